// round 6
// baseline (speedup 1.0000x reference)
#include <cuda_runtime.h>
#include <cuda_fp16.h>
#include <cstdint>

// ============================================================================
// LoRALayer: out[16384,4096] = x[16384,4096] @ W_eff^T + bias
//   W_eff[o,d] = weight[o,d] + sum_r A[d,r]*B[r,o]
// sm_103 (non-'a' PTX): legacy mma.sync fp16 HMMA.
// R6: fp16-ACCUM HMMA (2x rate on the legacy pipe) with hybrid accumulation:
//   fp16 accum over K-chunks of 64 (4 MMAs, C=0 on the first), then promote
//   into fp32 master accumulators. Extra error ~2.2e-4 -> total ~3.7e-4.
// ============================================================================

#define DINL __device__ __forceinline__

constexpr int M_DIM = 16384;
constexpr int N_DIM = 4096;
constexpr int K_DIM = 4096;
constexpr int RANK  = 16;

constexpr int BM = 128;
constexpr int BN = 256;
constexpr int BK = 64;
constexpr int NKI = K_DIM / BK;           // 64 k-iterations
constexpr int STAGES = 4;

// per-stage smem (fp16, 128B rows): XH[128][64] WH[256][64]
constexpr int OFF_XH = 0;
constexpr int OFF_WH = 16384;
constexpr int STAGE_B = 49152;
constexpr int SMEM_BYTES = STAGES * STAGE_B;   // 196608

// ---------------- scratch (device globals; no runtime allocation) ----------
__device__ __half g_xh[(size_t)M_DIM * K_DIM];
__device__ __half g_wh[(size_t)N_DIM * K_DIM];

// ---------------- helpers ---------------------------------------------------
DINL uint32_t smem_u32(const void* p) {
    uint32_t a;
    asm("{ .reg .u64 t; cvta.to.shared.u64 t, %1; cvt.u32.u64 %0, t; }"
        : "=r"(a) : "l"(p));
    return a;
}
// SW128 swizzle for 128-byte rows (Swizzle<3,4,3>)
DINL uint32_t swz(uint32_t x) { return x ^ ((x >> 3) & 0x70); }

DINL void cp16(uint32_t dst, const void* src) {
    asm volatile("cp.async.cg.shared.global [%0], [%1], 16;"
                 :: "r"(dst), "l"(src) : "memory");
}
#define CP_COMMIT() asm volatile("cp.async.commit_group;" ::: "memory")
#define CP_WAIT2()  asm volatile("cp.async.wait_group 2;" ::: "memory")

DINL void ldm4(uint32_t* r, uint32_t addr) {
    asm volatile("ldmatrix.sync.aligned.m8n8.x4.shared.b16 {%0,%1,%2,%3}, [%4];"
                 : "=r"(r[0]), "=r"(r[1]), "=r"(r[2]), "=r"(r[3]) : "r"(addr));
}
// fp16-accum MMA: init form (C = 0)
DINL void mma_h_init(uint32_t* d, const uint32_t* a, uint32_t b0, uint32_t b1) {
    asm volatile(
        "mma.sync.aligned.m16n8k16.row.col.f16.f16.f16.f16 "
        "{%0,%1}, {%2,%3,%4,%5}, {%6,%7}, {%8,%9};"
        : "=r"(d[0]), "=r"(d[1])
        : "r"(a[0]), "r"(a[1]), "r"(a[2]), "r"(a[3]),
          "r"(b0), "r"(b1), "r"(0u), "r"(0u));
}
// fp16-accum MMA: accumulate form (C = D)
DINL void mma_h_acc(uint32_t* d, const uint32_t* a, uint32_t b0, uint32_t b1) {
    asm volatile(
        "mma.sync.aligned.m16n8k16.row.col.f16.f16.f16.f16 "
        "{%0,%1}, {%2,%3,%4,%5}, {%6,%7}, {%0,%1};"
        : "+r"(d[0]), "+r"(d[1])
        : "r"(a[0]), "r"(a[1]), "r"(a[2]), "r"(a[3]), "r"(b0), "r"(b1));
}

// ============================================================================
// Kernel 1: x (fp32) -> fp16, row-major [M][K]
// ============================================================================
__global__ void __launch_bounds__(256) split_x_kernel(const float* __restrict__ x) {
    size_t e = ((size_t)blockIdx.x * blockDim.x + threadIdx.x) * 8;
    const float4* p = reinterpret_cast<const float4*>(x + e);
    float4 v0 = p[0], v1 = p[1];
    float vv[8] = {v0.x, v0.y, v0.z, v0.w, v1.x, v1.y, v1.z, v1.w};
    __half h[8];
#pragma unroll
    for (int i = 0; i < 8; i++) h[i] = __float2half_rn(vv[i]);
    *reinterpret_cast<uint4*>(g_xh + e) = *reinterpret_cast<uint4*>(h);
}

// ============================================================================
// Kernel 2: W_eff = W + A@B -> fp16, row-major [N][K]
// ============================================================================
__global__ void __launch_bounds__(256) build_w_kernel(
    const float* __restrict__ weight,   // [N,K] row-major
    const float* __restrict__ A,        // [K,RANK]
    const float* __restrict__ B)        // [RANK,N]
{
    __shared__ float As[64][RANK];
    __shared__ float Bs[RANK][256];

    int kblk = blockIdx.x, nblk = blockIdx.y;
    int d0 = kblk * 64, o0 = nblk * 256;
    int tid = threadIdx.x;

    reinterpret_cast<float4*>(&As[0][0])[tid] =
        reinterpret_cast<const float4*>(A + (size_t)d0 * RANK)[tid];
#pragma unroll
    for (int r = 0; r < RANK; r++)
        Bs[r][tid] = B[(size_t)r * N_DIM + o0 + tid];
    __syncthreads();

    int o = o0 + tid;
    const float* wrow = weight + (size_t)o * K_DIM + d0;

#pragma unroll 1
    for (int dc = 0; dc < 64; dc += 8) {
        float4 wa = reinterpret_cast<const float4*>(wrow + dc)[0];
        float4 wb = reinterpret_cast<const float4*>(wrow + dc)[1];
        float w[8] = {wa.x, wa.y, wa.z, wa.w, wb.x, wb.y, wb.z, wb.w};
        __half h[8];
#pragma unroll
        for (int i = 0; i < 8; i++) {
            float s = 0.f;
#pragma unroll
            for (int r = 0; r < RANK; r++) s += As[dc + i][r] * Bs[r][tid];
            h[i] = __float2half_rn(w[i] + s);
        }
        *reinterpret_cast<uint4*>(g_wh + (size_t)o * K_DIM + d0 + dc) =
            *reinterpret_cast<uint4*>(h);
    }
}

// ============================================================================
// Kernel 3: GEMM. CTA = 128x256, 256 thr (8 warps, 64x64 warp tiles),
// BK=64, 4-stage cp.async pipeline, fp16-accum MMA + fp32 master accum.
// Per BK-iter: two nt-halves; per half: 4 kc of MMAs into fp16 accums
// (first kc uses C=0), then promote into fp32 masters.
// ============================================================================
__global__ void __launch_bounds__(256, 1)
gemm_kernel(const float* __restrict__ bias, float* __restrict__ out)
{
    extern __shared__ __align__(1024) char smem[];
    const uint32_t sbase = smem_u32(smem);

    const int tid  = threadIdx.x;
    const int wid  = tid >> 5;
    const int lane = tid & 31;

    // wave-grouped ordering: 16 groups of (8 m) x (16 n) = 128 CTAs/group
    const int bid  = blockIdx.x;
    const int grp  = bid >> 7;
    const int mblk = grp * 8 + ((bid >> 4) & 7);
    const int nblk = bid & 15;

    const int m_base = (wid >> 2) * 64;   // 0 or 64
    const int n_base = (wid & 3) * 64;    // 0,64,128,192

    // ldmatrix lane-relative mapping
    const int r16   = (lane & 7) + ((lane >> 3) & 1) * 8;
    const int chalf = lane >> 4;          // 0 or 1 (16B chunk within k16)

    // ---------------- stage loader (256 threads) ----------------
    auto load_stage = [&](int buf, int kblk) {
        if (kblk < NKI) {
            uint32_t sb = sbase + buf * STAGE_B;
            int k0 = kblk * BK;
#pragma unroll
            for (int i = 0; i < 4; i++) {           // X: 1024 16B chunks
                int q = tid + i * 256;
                int m = q >> 3, c = q & 7;
                uint32_t so = swz((uint32_t)(m * 128 + c * 16));
                size_t g = (size_t)(mblk * BM + m) * K_DIM + k0 + c * 8;
                cp16(sb + OFF_XH + so, g_xh + g);
            }
#pragma unroll
            for (int i = 0; i < 8; i++) {           // W: 2048 16B chunks
                int q = tid + i * 256;
                int n = q >> 3, c = q & 7;
                uint32_t so = swz((uint32_t)(n * 128 + c * 16));
                size_t g = (size_t)(nblk * BN + n) * K_DIM + k0 + c * 8;
                cp16(sb + OFF_WH + so, g_wh + g);
            }
        }
        CP_COMMIT();
    };

    float acc[4][8][4];
#pragma unroll
    for (int mt = 0; mt < 4; mt++)
#pragma unroll
        for (int nt = 0; nt < 8; nt++)
#pragma unroll
            for (int q = 0; q < 4; q++) acc[mt][nt][q] = 0.f;

    load_stage(0, 0);
    load_stage(1, 1);
    load_stage(2, 2);

#pragma unroll 1
    for (int it = 0; it < NKI; it++) {
        CP_WAIT2();
        __syncthreads();
        load_stage((it + 3) & 3, it + 3);

        uint32_t sb = sbase + (it & 3) * STAGE_B;

#pragma unroll
        for (int nh = 0; nh < 2; nh++) {          // nt half: cols nh*32..+31
            uint32_t ah[4][4][2];                 // fp16x2 accums for chunk

#pragma unroll
            for (int kc = 0; kc < 4; kc++) {
                const int acol = 2 * kc + chalf;
                uint32_t xa[4][4], wf[2][4];

#pragma unroll
                for (int mt = 0; mt < 4; mt++)
                    ldm4(xa[mt], sb + OFF_XH +
                         swz((uint32_t)((m_base + mt * 16 + r16) * 128 + acol * 16)));
#pragma unroll
                for (int t = 0; t < 2; t++)
                    ldm4(wf[t], sb + OFF_WH +
                         swz((uint32_t)((n_base + nh * 32 + t * 16 + r16) * 128 + acol * 16)));

                if (kc == 0) {
#pragma unroll
                    for (int mt = 0; mt < 4; mt++)
#pragma unroll
                        for (int nl = 0; nl < 4; nl++)
                            mma_h_init(ah[mt][nl], xa[mt],
                                       wf[nl >> 1][nl & 1], wf[nl >> 1][(nl & 1) + 2]);
                } else {
#pragma unroll
                    for (int mt = 0; mt < 4; mt++)
#pragma unroll
                        for (int nl = 0; nl < 4; nl++)
                            mma_h_acc(ah[mt][nl], xa[mt],
                                      wf[nl >> 1][nl & 1], wf[nl >> 1][(nl & 1) + 2]);
                }
            }

            // promote fp16 chunk accums into fp32 masters
#pragma unroll
            for (int mt = 0; mt < 4; mt++)
#pragma unroll
                for (int nl = 0; nl < 4; nl++) {
                    float2 f0 = __half22float2(
                        *reinterpret_cast<__half2*>(&ah[mt][nl][0]));
                    float2 f1 = __half22float2(
                        *reinterpret_cast<__half2*>(&ah[mt][nl][1]));
                    float* a4 = acc[mt][nh * 4 + nl];
                    a4[0] += f0.x; a4[1] += f0.y;
                    a4[2] += f1.x; a4[3] += f1.y;
                }
        }
    }

    // ---------------- epilogue: bias add + fp32 store ----------------
    const int gm = mblk * BM + m_base;
    const int gn = nblk * BN + n_base;
#pragma unroll
    for (int nt = 0; nt < 8; nt++) {
        int col = gn + nt * 8 + 2 * (lane & 3);
        float2 bv = *reinterpret_cast<const float2*>(bias + col);
#pragma unroll
        for (int mt = 0; mt < 4; mt++) {
            int row0 = gm + mt * 16 + (lane >> 2);
            float2 v0 = {acc[mt][nt][0] + bv.x, acc[mt][nt][1] + bv.y};
            float2 v1 = {acc[mt][nt][2] + bv.x, acc[mt][nt][3] + bv.y};
            *reinterpret_cast<float2*>(out + (size_t)row0 * N_DIM + col) = v0;
            *reinterpret_cast<float2*>(out + (size_t)(row0 + 8) * N_DIM + col) = v1;
        }
    }
}

// ============================================================================
// Launch
// ============================================================================
extern "C" void kernel_launch(void* const* d_in, const int* in_sizes, int n_in,
                              void* d_out, int out_size)
{
    const float* x      = (const float*)d_in[0];
    const float* A      = (const float*)d_in[1];
    const float* B      = (const float*)d_in[2];
    const float* weight = (const float*)d_in[3];
    const float* bias   = (const float*)d_in[4];
    float* out = (float*)d_out;

    cudaFuncSetAttribute(gemm_kernel,
                         cudaFuncAttributeMaxDynamicSharedMemorySize, SMEM_BYTES);

    split_x_kernel<<<(int)(((size_t)M_DIM * K_DIM) / 8 / 256), 256>>>(x);
    build_w_kernel<<<dim3(K_DIM / 64, N_DIM / 256), 256>>>(weight, A, B);
    gemm_kernel<<<(M_DIM / BM) * (N_DIM / BN), 256, SMEM_BYTES>>>(bias, out);
}

// round 7
// speedup vs baseline: 1.4438x; 1.4438x over previous
#include <cuda_runtime.h>
#include <cuda_fp16.h>
#include <cstdint>

// ============================================================================
// LoRALayer: out[16384,4096] = x[16384,4096] @ W_eff^T + bias
//   W_eff[o,d] = weight[o,d] + sum_r A[d,r]*B[r,o]
// sm_103 (non-'a' PTX): legacy mma.sync fp16 HMMA, fp32 accum, 1 pass.
// R7: R5 core + (a) fused prep kernel, (b) double-buffered fragment
// pipelining across kc and iteration boundaries (wait_group 1 exposes
// stage it+1 one iteration early, so next-iter frags prefetch under MMAs).
// ============================================================================

#define DINL __device__ __forceinline__

constexpr int M_DIM = 16384;
constexpr int N_DIM = 4096;
constexpr int K_DIM = 4096;
constexpr int RANK  = 16;

constexpr int BM = 128;
constexpr int BN = 256;
constexpr int BK = 64;
constexpr int NKI = K_DIM / BK;           // 64 k-iterations
constexpr int STAGES = 4;

// per-stage smem (fp16, 128B rows): XH[128][64] WH[256][64]
constexpr int OFF_XH = 0;
constexpr int OFF_WH = 16384;
constexpr int STAGE_B = 49152;
constexpr int SMEM_BYTES = STAGES * STAGE_B;   // 196608

constexpr int SPLIT_BLOCKS = (int)(((size_t)M_DIM * K_DIM) / 8 / 256);  // 32768
constexpr int BUILD_BLOCKS = (K_DIM / 64) * (N_DIM / 256);              // 1024

// ---------------- scratch (device globals; no runtime allocation) ----------
__device__ __half g_xh[(size_t)M_DIM * K_DIM];
__device__ __half g_wh[(size_t)N_DIM * K_DIM];

// ---------------- helpers ---------------------------------------------------
DINL uint32_t smem_u32(const void* p) {
    uint32_t a;
    asm("{ .reg .u64 t; cvta.to.shared.u64 t, %1; cvt.u32.u64 %0, t; }"
        : "=r"(a) : "l"(p));
    return a;
}
// SW128 swizzle for 128-byte rows (Swizzle<3,4,3>)
DINL uint32_t swz(uint32_t x) { return x ^ ((x >> 3) & 0x70); }

DINL void cp16(uint32_t dst, const void* src) {
    asm volatile("cp.async.cg.shared.global [%0], [%1], 16;"
                 :: "r"(dst), "l"(src) : "memory");
}
#define CP_COMMIT() asm volatile("cp.async.commit_group;" ::: "memory")
#define CP_WAIT1()  asm volatile("cp.async.wait_group 1;" ::: "memory")

DINL void ldm4(uint32_t* r, uint32_t addr) {
    asm volatile("ldmatrix.sync.aligned.m8n8.x4.shared.b16 {%0,%1,%2,%3}, [%4];"
                 : "=r"(r[0]), "=r"(r[1]), "=r"(r[2]), "=r"(r[3]) : "r"(addr));
}
DINL void mma16816(float* c, const uint32_t* a, uint32_t b0, uint32_t b1) {
    asm volatile(
        "mma.sync.aligned.m16n8k16.row.col.f32.f16.f16.f32 "
        "{%0,%1,%2,%3}, {%4,%5,%6,%7}, {%8,%9}, {%0,%1,%2,%3};"
        : "+f"(c[0]), "+f"(c[1]), "+f"(c[2]), "+f"(c[3])
        : "r"(a[0]), "r"(a[1]), "r"(a[2]), "r"(a[3]), "r"(b0), "r"(b1));
}

// ============================================================================
// Kernel 1 (fused prep): blocks [0, SPLIT_BLOCKS) convert x -> fp16;
// blocks [SPLIT_BLOCKS, +BUILD_BLOCKS) build W_eff = W + A@B -> fp16.
// Independent, both memory-bound -> run concurrently in one launch.
// ============================================================================
__global__ void __launch_bounds__(256) prep_kernel(
    const float* __restrict__ x,
    const float* __restrict__ weight,   // [N,K] row-major
    const float* __restrict__ A,        // [K,RANK]
    const float* __restrict__ B)        // [RANK,N]
{
    __shared__ float As[64][RANK];
    __shared__ float Bs[RANK][256];

    int tid = threadIdx.x;

    if (blockIdx.x < SPLIT_BLOCKS) {
        size_t e = ((size_t)blockIdx.x * 256 + tid) * 8;
        const float4* p = reinterpret_cast<const float4*>(x + e);
        float4 v0 = p[0], v1 = p[1];
        float vv[8] = {v0.x, v0.y, v0.z, v0.w, v1.x, v1.y, v1.z, v1.w};
        __half h[8];
#pragma unroll
        for (int i = 0; i < 8; i++) h[i] = __float2half_rn(vv[i]);
        *reinterpret_cast<uint4*>(g_xh + e) = *reinterpret_cast<uint4*>(h);
        return;
    }

    int bid2 = blockIdx.x - SPLIT_BLOCKS;
    int kblk = bid2 & 63, nblk = bid2 >> 6;
    int d0 = kblk * 64, o0 = nblk * 256;

    reinterpret_cast<float4*>(&As[0][0])[tid] =
        reinterpret_cast<const float4*>(A + (size_t)d0 * RANK)[tid];
#pragma unroll
    for (int r = 0; r < RANK; r++)
        Bs[r][tid] = B[(size_t)r * N_DIM + o0 + tid];
    __syncthreads();

    int o = o0 + tid;
    const float* wrow = weight + (size_t)o * K_DIM + d0;

#pragma unroll 1
    for (int dc = 0; dc < 64; dc += 8) {
        float4 wa = reinterpret_cast<const float4*>(wrow + dc)[0];
        float4 wb = reinterpret_cast<const float4*>(wrow + dc)[1];
        float w[8] = {wa.x, wa.y, wa.z, wa.w, wb.x, wb.y, wb.z, wb.w};
        __half h[8];
#pragma unroll
        for (int i = 0; i < 8; i++) {
            float s = 0.f;
#pragma unroll
            for (int r = 0; r < RANK; r++) s += As[dc + i][r] * Bs[r][tid];
            h[i] = __float2half_rn(w[i] + s);
        }
        *reinterpret_cast<uint4*>(g_wh + (size_t)o * K_DIM + d0 + dc) =
            *reinterpret_cast<uint4*>(h);
    }
}

// ============================================================================
// Kernel 2: GEMM. CTA = 128x256, 256 thr (8 warps, 64x64 warp tiles),
// BK=64, 4-stage cp.async, fp16 mma -> fp32 accum, 1 pass.
// Fragment double-buffering across kc AND iteration boundaries.
// ============================================================================
__global__ void __launch_bounds__(256, 1)
gemm_kernel(const float* __restrict__ bias, float* __restrict__ out)
{
    extern __shared__ __align__(1024) char smem[];
    const uint32_t sbase = smem_u32(smem);

    const int tid  = threadIdx.x;
    const int wid  = tid >> 5;
    const int lane = tid & 31;

    // wave-grouped ordering: 16 groups of (8 m) x (16 n) = 128 CTAs/group
    const int bid  = blockIdx.x;
    const int grp  = bid >> 7;
    const int mblk = grp * 8 + ((bid >> 4) & 7);
    const int nblk = bid & 15;

    const int m_base = (wid >> 2) * 64;   // 0 or 64
    const int n_base = (wid & 3) * 64;    // 0,64,128,192

    // ldmatrix lane-relative mapping
    const int r16   = (lane & 7) + ((lane >> 3) & 1) * 8;
    const int chalf = lane >> 4;          // 0 or 1 (16B chunk within k16)

    // ---------------- stage loader (256 threads) ----------------
    auto load_stage = [&](int buf, int kblk) {
        if (kblk < NKI) {
            uint32_t sb = sbase + buf * STAGE_B;
            int k0 = kblk * BK;
#pragma unroll
            for (int i = 0; i < 4; i++) {           // X: 1024 16B chunks
                int q = tid + i * 256;
                int m = q >> 3, c = q & 7;
                uint32_t so = swz((uint32_t)(m * 128 + c * 16));
                size_t g = (size_t)(mblk * BM + m) * K_DIM + k0 + c * 8;
                cp16(sb + OFF_XH + so, g_xh + g);
            }
#pragma unroll
            for (int i = 0; i < 8; i++) {           // W: 2048 16B chunks
                int q = tid + i * 256;
                int n = q >> 3, c = q & 7;
                uint32_t so = swz((uint32_t)(n * 128 + c * 16));
                size_t g = (size_t)(nblk * BN + n) * K_DIM + k0 + c * 8;
                cp16(sb + OFF_WH + so, g_wh + g);
            }
        }
        CP_COMMIT();
    };

    auto xaddr = [&](uint32_t sb, int mt, int acol) {
        return sb + OFF_XH +
               swz((uint32_t)((m_base + mt * 16 + r16) * 128 + acol * 16));
    };
    auto waddr = [&](uint32_t sb, int t, int acol) {
        return sb + OFF_WH +
               swz((uint32_t)((n_base + t * 16 + r16) * 128 + acol * 16));
    };

    float acc[4][8][4];
#pragma unroll
    for (int mt = 0; mt < 4; mt++)
#pragma unroll
        for (int nt = 0; nt < 8; nt++)
#pragma unroll
            for (int q = 0; q < 4; q++) acc[mt][nt][q] = 0.f;

    load_stage(0, 0);
    load_stage(1, 1);
    load_stage(2, 2);
    CP_WAIT1();                 // completes stages 0 and 1
    __syncthreads();

    uint32_t xa[2][4][4], wf[2][4][4];
#pragma unroll
    for (int mt = 0; mt < 4; mt++) ldm4(xa[0][mt], xaddr(sbase, mt, chalf));
#pragma unroll
    for (int t = 0; t < 4; t++)  ldm4(wf[0][t],  waddr(sbase, t, chalf));

#pragma unroll 1
    for (int it = 0; it < NKI; it++) {
        uint32_t sb  = sbase + (it & 3) * STAGE_B;
        uint32_t sbn = sbase + ((it + 1) & 3) * STAGE_B;

#pragma unroll
        for (int kc = 0; kc < 4; kc++) {
            const int cur = kc & 1, nxt = cur ^ 1;
            const uint32_t psb = (kc < 3) ? sb : sbn;           // prefetch src
            const int      pac = (kc < 3) ? (2 * (kc + 1) + chalf) : chalf;

            // 16 MMAs (mt 0..1)
#pragma unroll
            for (int mt = 0; mt < 2; mt++)
#pragma unroll
                for (int nt = 0; nt < 8; nt++)
                    mma16816(acc[mt][nt], xa[cur][mt],
                             wf[cur][nt >> 1][nt & 1], wf[cur][nt >> 1][(nt & 1) + 2]);

            // prefetch next X frags under the MMA stream
#pragma unroll
            for (int mt = 0; mt < 4; mt++)
                ldm4(xa[nxt][mt], xaddr(psb, mt, pac));

            // 16 MMAs (mt 2..3)
#pragma unroll
            for (int mt = 2; mt < 4; mt++)
#pragma unroll
                for (int nt = 0; nt < 8; nt++)
                    mma16816(acc[mt][nt], xa[cur][mt],
                             wf[cur][nt >> 1][nt & 1], wf[cur][nt >> 1][(nt & 1) + 2]);

            // prefetch next W frags
#pragma unroll
            for (int t = 0; t < 4; t++)
                ldm4(wf[nxt][t], waddr(psb, t, pac));
        }

        // issue next stage load; keep <=1 group outstanding so stage it+2
        // is complete (and visible after the barrier) entering iter it+1.
        load_stage((it + 3) & 3, it + 3);
        CP_WAIT1();
        __syncthreads();
    }

    // ---------------- epilogue: bias add + fp32 store ----------------
    const int gm = mblk * BM + m_base;
    const int gn = nblk * BN + n_base;
#pragma unroll
    for (int nt = 0; nt < 8; nt++) {
        int col = gn + nt * 8 + 2 * (lane & 3);
        float2 bv = *reinterpret_cast<const float2*>(bias + col);
#pragma unroll
        for (int mt = 0; mt < 4; mt++) {
            int row0 = gm + mt * 16 + (lane >> 2);
            float2 v0 = {acc[mt][nt][0] + bv.x, acc[mt][nt][1] + bv.y};
            float2 v1 = {acc[mt][nt][2] + bv.x, acc[mt][nt][3] + bv.y};
            *reinterpret_cast<float2*>(out + (size_t)row0 * N_DIM + col) = v0;
            *reinterpret_cast<float2*>(out + (size_t)(row0 + 8) * N_DIM + col) = v1;
        }
    }
}

// ============================================================================
// Launch
// ============================================================================
extern "C" void kernel_launch(void* const* d_in, const int* in_sizes, int n_in,
                              void* d_out, int out_size)
{
    const float* x      = (const float*)d_in[0];
    const float* A      = (const float*)d_in[1];
    const float* B      = (const float*)d_in[2];
    const float* weight = (const float*)d_in[3];
    const float* bias   = (const float*)d_in[4];
    float* out = (float*)d_out;

    cudaFuncSetAttribute(gemm_kernel,
                         cudaFuncAttributeMaxDynamicSharedMemorySize, SMEM_BYTES);

    prep_kernel<<<SPLIT_BLOCKS + BUILD_BLOCKS, 256>>>(x, weight, A, B);
    gemm_kernel<<<(M_DIM / BM) * (N_DIM / BN), 256, SMEM_BYTES>>>(bias, out);
}